// round 6
// baseline (speedup 1.0000x reference)
#include <cuda_runtime.h>
#include <math_constants.h>

#define HH 1024
#define WW 1024
#define NB 16
#define NPIX (NB * HH * WW)
#define TH 32
#define NOUT 6
#define FULLM 0xffffffffu

__device__ __align__(256) float g_bufA[NPIX];
__device__ __align__(256) float g_bufB[NPIX];

#define C1 (1.0f / 24.0f)
#define C3 (3.0f / 24.0f)
#define C7 (7.0f / 24.0f)
#define NEGINF (-CUDART_INF_F)

typedef unsigned long long u64;

#define PK2(d, lo, hi)  asm("mov.b64 %0, {%1, %2};" : "=l"(d) : "f"(lo), "f"(hi))
#define UPK2(lo, hi, s) asm("mov.b64 {%0, %1}, %2;" : "=f"(lo), "=f"(hi) : "l"(s))
#define ADD2(d, a, b)   asm("add.rn.f32x2 %0, %1, %2;" : "=l"(d) : "l"(a), "l"(b))
#define ACC2(d, b)      asm("add.rn.f32x2 %0, %0, %1;" : "+l"(d) : "l"(b))
#define MUL2(d, a, b)   asm("mul.rn.f32x2 %0, %1, %2;" : "=l"(d) : "l"(a), "l"(b))
#define FMA2(d, a, b, c) asm("fma.rn.f32x2 %0, %1, %2, %3;" : "=l"(d) : "l"(a), "l"(b), "l"(c))

// ---- window shuffles (w[0..9] = cols c0-3 .. c0+6; edges fixed by caller) ----
__device__ __forceinline__ void wshuf(float4 own, float w[10]) {
    w[3] = own.x; w[4] = own.y; w[5] = own.z; w[6] = own.w;
    w[0] = __shfl_up_sync(FULLM, own.y, 1);
    w[1] = __shfl_up_sync(FULLM, own.z, 1);
    w[2] = __shfl_up_sync(FULLM, own.w, 1);
    w[7] = __shfl_down_sync(FULLM, own.x, 1);
    w[8] = __shfl_down_sync(FULLM, own.y, 1);
    w[9] = __shfl_down_sync(FULLM, own.z, 1);
}

// ---- packed filter + ring accumulate; returns completed slot in raw[4] ----
template<int U>
__device__ __forceinline__ void filt(const float w[10], u64 a[7][2],
                                     u64 kC1, u64 kC3, u64 kM7, u64 kM1,
                                     float raw[4])
{
    u64 P[9];
    #pragma unroll
    for (int j = 0; j < 9; ++j) PK2(P[j], w[j], w[j + 1]);

    #pragma unroll
    for (int p = 0; p < 2; ++p) {
        const int o = 2 * p;
        u64 t1, Pt, Puu, Pvv, Px2;
        ADD2(t1, P[2 + o], P[3 + o]);
        ADD2(Pt, t1, P[4 + o]);
        ADD2(Puu, P[1 + o], P[5 + o]);
        ADD2(Pvv, P[0 + o], P[6 + o]);
        ADD2(Px2, P[2 + o], P[4 + o]);

        u64 hA, hB, hC, hD, m1, m2, m3, i1, i2, i3;
        MUL2(hA, kC1, Pt);
        MUL2(m1, kC1, Puu);
        FMA2(hB, kC3, Pt, m1);
        MUL2(m2, kC1, P[0 + o]);
        FMA2(i1, kM7, P[3 + o], m2);
        FMA2(hC, kC3, Puu, i1);
        MUL2(m3, kC1, Pvv);
        FMA2(i2, kM7, Px2, m3);
        FMA2(i3, kC3, Puu, i2);
        FMA2(hD, kM1, P[3 + o], i3);

        ACC2(a[(U + 0) % 7][p], hA);
        ACC2(a[(U + 1) % 7][p], hB);
        ACC2(a[(U + 2) % 7][p], hC);
        ACC2(a[(U + 3) % 7][p], hD);
        ACC2(a[(U + 4) % 7][p], hC);
        ACC2(a[(U + 5) % 7][p], hB);
        ACC2(a[(U + 6) % 7][p], hA);
    }
    UPK2(raw[0], raw[1], a[U % 7][0]);
    UPK2(raw[2], raw[3], a[U % 7][1]);
    a[U % 7][0] = 0ull;
    a[U % 7][1] = 0ull;
}

// ===================== INTERIOR kernel (no bounds checks) =====================
struct StI {
    u64 a[7][2];
    float4 ownN;
    float extN;        // FIN only: scalar halo (lane0: c0-1, lane31: c0+4)
    float cp[4], pm[4];
    int bpp1, bpp2;    // FIN: byte-packed bit history
};

template<int U, bool FIN, bool VM, bool WR>
__device__ __forceinline__ void step_int(StI& s, const float*& p0, const float*& pe,
                                         float*& wp, int lane, bool writeok, int dup,
                                         u64 kC1, u64 kC3, u64 kM7, u64 kM1)
{
    float4 own = s.ownN;
    float extv = s.extN;
    s.ownN = *reinterpret_cast<const float4*>(p0);
    if (FIN && (lane == 0 || lane == 31)) s.extN = *pe;
    p0 += WW; pe += WW;

    float w[10];
    wshuf(own, w);
    if (lane == 0)  { w[0] = 0.f; w[1] = 0.f; w[2] = FIN ? extv : 0.f; }
    if (lane == 31) { w[7] = FIN ? extv : 0.f; w[8] = 0.f; w[9] = 0.f; }

    float raw[4];
    filt<U>(w, s.a, kC1, kC3, kM7, kM1, raw);

    if (VM) {
        float vm[4];
        #pragma unroll
        for (int k = 0; k < 4; ++k) {
            vm[k]  = fmaxf(s.pm[k], raw[k]);
            s.pm[k] = fmaxf(raw[k], s.cp[k]);
            s.cp[k] = raw[k];
        }
        float vmL = __shfl_up_sync(FULLM, vm[3], 1);
        float vmR = __shfl_down_sync(FULLM, vm[0], 1);
        float m0 = fmaxf(vmL,   fmaxf(vm[0], vm[1]));
        float m1 = fmaxf(vm[0], fmaxf(vm[1], vm[2]));
        float m2 = fmaxf(vm[1], fmaxf(vm[2], vm[3]));
        float m3 = fmaxf(vm[2], fmaxf(vm[3], vmR));

        if (!FIN) {
            if (WR && writeok)
                *reinterpret_cast<float4*>(wp) = make_float4(m0, m1, m2, m3);
        } else {
            int bp = (m0 > 0.5f ? 1 : 0) | ((m1 > 0.5f ? 1 : 0) << 8)
                   | ((m2 > 0.5f ? 1 : 0) << 16) | ((m3 > 0.5f ? 1 : 0) << 24);
            int sp_ = s.bpp2 + s.bpp1 + bp;     // per-byte counts <= 3, carry-free
            s.bpp2 = s.bpp1; s.bpp1 = bp;
            int sLp = __shfl_up_sync(FULLM, sp_, 1);
            int sRp = __shfl_down_sync(FULLM, sp_, 1);
            if (WR && writeok) {
                unsigned u = (unsigned)sp_;
                int s0 = u & 0xFF, s1 = (u >> 8) & 0xFF,
                    s2 = (u >> 16) & 0xFF, s3 = u >> 24;
                int n0 = (int)(((unsigned)sLp) >> 24) + s0 + s1;
                int n1 = s0 + s1 + s2;
                int n2 = s1 + s2 + s3;
                int n3 = s2 + s3 + (sRp & 0xFF);
                float4 o = make_float4(n0 >= 8 ? 1.f : 0.f, n1 >= 8 ? 1.f : 0.f,
                                       n2 >= 8 ? 1.f : 0.f, n3 >= 8 ? 1.f : 0.f);
                *reinterpret_cast<float4*>(wp) = o;
                if (dup) *reinterpret_cast<float4*>(wp + NPIX) = o;
            }
        }
        wp += WW;
    }
}

template<bool FIN>
__global__ void __launch_bounds__(32, 24) sweep_int(const float* __restrict__ src,
                                                    float* __restrict__ dst,
                                                    int dup)
{
    const int lane = threadIdx.x;
    const int sx = blockIdx.x + 1;          // interior strips 1..7
    const int Y0 = (blockIdx.y + 1) * TH;   // interior chunks 1..30
    const int b  = blockIdx.z;
    const int c0 = 120 * sx - 4 + 4 * lane;
    const float* sp = src + (size_t)b * HH * WW;
    float* dp = dst + (size_t)b * HH * WW;
    const bool writeok = (lane >= 1) && (lane <= 30);

    u64 kC1, kC3, kM7, kM1;
    PK2(kC1, C1, C1); PK2(kC3, C3, C3); PK2(kM7, -C7, -C7); PK2(kM1, -1.0f, -1.0f);

    StI s;
    #pragma unroll
    for (int i = 0; i < 7; ++i) { s.a[i][0] = 0ull; s.a[i][1] = 0ull; }
    #pragma unroll
    for (int k = 0; k < 4; ++k) { s.cp[k] = NEGINF; s.pm[k] = NEGINF; }
    s.bpp1 = 0; s.bpp2 = 0;

    const int rs = FIN ? (Y0 - 5) : (Y0 - 4);
    const int ec = (lane == 0) ? (c0 - 1) : (c0 + 4);
    s.ownN = *reinterpret_cast<const float4*>(sp + (size_t)rs * WW + c0);
    s.extN = 0.f;
    if (FIN && (lane == 0 || lane == 31))
        s.extN = sp[(size_t)rs * WW + ec];

    const float* p0 = sp + (size_t)(rs + 1) * WW + c0;
    const float* pe = sp + (size_t)(rs + 1) * WW + ec;
    float* wp = dp + (size_t)(FIN ? (Y0 - 4) : (Y0 - 2)) * WW + c0;

    #define SI(UU, VMf, WRf) \
        step_int<UU, FIN, VMf, WRf>(s, p0, pe, wp, lane, writeok, dup, kC1, kC3, kM7, kM1);

    if (!FIN) {
        SI(0,false,false) SI(1,false,false) SI(2,false,false)
        SI(3,false,false) SI(4,false,false) SI(5,false,false)
        SI(6,true,false)  SI(0,true,false)
        #pragma unroll 1
        for (int g = 0; g < 4; ++g) {
            SI(1,true,true) SI(2,true,true) SI(3,true,true) SI(4,true,true)
            SI(5,true,true) SI(6,true,true) SI(0,true,true)
        }
        SI(1,true,true) SI(2,true,true) SI(3,true,true) SI(4,true,true)
    } else {
        SI(0,false,false) SI(1,false,false) SI(2,false,false)
        SI(3,false,false) SI(4,false,false) SI(5,false,false)
        SI(6,true,false)  SI(0,true,false) SI(1,true,false) SI(2,true,false)
        #pragma unroll 1
        for (int g = 0; g < 4; ++g) {
            SI(3,true,true) SI(4,true,true) SI(5,true,true) SI(6,true,true)
            SI(0,true,true) SI(1,true,true) SI(2,true,true)
        }
        SI(3,true,true) SI(4,true,true) SI(5,true,true) SI(6,true,true)
    }
    #undef SI
}

// ===================== EDGE kernel (generic guarded path) =====================
struct StG {
    u64 a[7][2];
    float4 ownN, extN;
    float cp[4], pm[4];
    int bp1[4], bp2[4];
};

__device__ __forceinline__ float4 ld4(const float* __restrict__ p, int r, int cc) {
    if ((unsigned)r < (unsigned)HH && (unsigned)cc < (unsigned)WW)
        return *reinterpret_cast<const float4*>(p + (size_t)r * WW + cc);
    return make_float4(0.f, 0.f, 0.f, 0.f);
}

template<int U, bool FIN>
__device__ __forceinline__ void step_gen(StG& s, const float* sp, float* dp, int r,
                                         int lane, int c0, int ecc, int Y0, int CFIRST,
                                         bool writeok, bool isEdge, const bool cv[4],
                                         int dup, u64 kC1, u64 kC3, u64 kM7, u64 kM1)
{
    float4 own = s.ownN, ext = s.extN;
    s.ownN = ld4(sp, r + 1, c0);
    s.extN = isEdge ? ld4(sp, r + 1, ecc) : make_float4(0.f, 0.f, 0.f, 0.f);

    float w[10];
    wshuf(own, w);
    if (lane == 0)  { w[0] = ext.y; w[1] = ext.z; w[2] = ext.w; }
    if (lane == 31) { w[7] = ext.x; w[8] = ext.y; w[9] = ext.z; }

    float raw[4];
    filt<U>(w, s.a, kC1, kC3, kM7, kM1, raw);

    const int cr = r - 3;
    if (cr >= CFIRST) {
        const bool rv = (unsigned)cr < (unsigned)HH;
        float cur[4], vm[4];
        #pragma unroll
        for (int k = 0; k < 4; ++k) {
            cur[k] = (rv && cv[k]) ? raw[k] : NEGINF;
            vm[k]  = fmaxf(s.pm[k], cur[k]);
            s.pm[k] = fmaxf(cur[k], s.cp[k]);
            s.cp[k] = cur[k];
        }
        float vmL = __shfl_up_sync(FULLM, vm[3], 1);
        float vmR = __shfl_down_sync(FULLM, vm[0], 1);
        float m0 = fmaxf(vmL,   fmaxf(vm[0], vm[1]));
        float m1 = fmaxf(vm[0], fmaxf(vm[1], vm[2]));
        float m2 = fmaxf(vm[1], fmaxf(vm[2], vm[3]));
        float m3 = fmaxf(vm[2], fmaxf(vm[3], vmR));
        const int v = cr - 1;

        if (!FIN) {
            if (writeok && v >= Y0 && v < Y0 + TH && v < HH)
                *reinterpret_cast<float4*>(dp + (size_t)v * WW + c0)
                    = make_float4(m0, m1, m2, m3);
        } else {
            const bool bv = (unsigned)v < (unsigned)HH;
            int b0 = (bv && cv[0] && m0 > 0.5f) ? 1 : 0;
            int b1 = (bv && cv[1] && m1 > 0.5f) ? 1 : 0;
            int b2 = (bv && cv[2] && m2 > 0.5f) ? 1 : 0;
            int b3 = (bv && cv[3] && m3 > 0.5f) ? 1 : 0;
            int s0 = s.bp2[0] + s.bp1[0] + b0;
            int s1 = s.bp2[1] + s.bp1[1] + b1;
            int s2 = s.bp2[2] + s.bp1[2] + b2;
            int s3 = s.bp2[3] + s.bp1[3] + b3;
            s.bp2[0] = s.bp1[0]; s.bp2[1] = s.bp1[1];
            s.bp2[2] = s.bp1[2]; s.bp2[3] = s.bp1[3];
            s.bp1[0] = b0; s.bp1[1] = b1; s.bp1[2] = b2; s.bp1[3] = b3;
            int sL = __shfl_up_sync(FULLM, s3, 1);
            int sR = __shfl_down_sync(FULLM, s0, 1);
            int n0 = sL + s0 + s1;
            int n1 = s0 + s1 + s2;
            int n2 = s1 + s2 + s3;
            int n3 = s2 + s3 + sR;
            const int wr = v - 1;
            if (writeok && wr >= Y0 && wr < Y0 + TH && (unsigned)wr < (unsigned)HH) {
                float4 o = make_float4(n0 >= 8 ? 1.f : 0.f, n1 >= 8 ? 1.f : 0.f,
                                       n2 >= 8 ? 1.f : 0.f, n3 >= 8 ? 1.f : 0.f);
                float* op = dp + (size_t)wr * WW + c0;
                *reinterpret_cast<float4*>(op) = o;
                if (dup) *reinterpret_cast<float4*>(op + NPIX) = o;
            }
        }
    }
}

template<bool FIN>
__global__ void __launch_bounds__(32) sweep_edge(const float* __restrict__ src,
                                                 float* __restrict__ dst,
                                                 int dup)
{
    const int sx = blockIdx.x;
    const int by = blockIdx.y;
    if (sx >= 1 && sx <= 7 && by >= 1 && by <= 30) return;   // interior handled elsewhere

    const int lane = threadIdx.x;
    const int Y0 = by * TH;
    const int b = blockIdx.z;
    const int c0 = 120 * sx - 4 + 4 * lane;
    const int ecc = (lane == 0) ? (c0 - 4) : (c0 + 4);
    const float* sp = src + (size_t)b * HH * WW;
    float* dp = dst + (size_t)b * HH * WW;
    const bool isEdge = (lane == 0) || (lane == 31);
    const bool writeok = (lane >= 1) && (lane <= 30) && (c0 < WW);
    bool cv[4];
    #pragma unroll
    for (int k = 0; k < 4; ++k) cv[k] = (unsigned)(c0 + k) < (unsigned)WW;
    const int CFIRST = FIN ? (Y0 - 2) : (Y0 - 1);

    u64 kC1, kC3, kM7, kM1;
    PK2(kC1, C1, C1); PK2(kC3, C3, C3); PK2(kM7, -C7, -C7); PK2(kM1, -1.0f, -1.0f);

    StG s;
    #pragma unroll
    for (int i = 0; i < 7; ++i) { s.a[i][0] = 0ull; s.a[i][1] = 0ull; }
    #pragma unroll
    for (int k = 0; k < 4; ++k) {
        s.cp[k] = NEGINF; s.pm[k] = NEGINF; s.bp1[k] = 0; s.bp2[k] = 0;
    }
    const int rs = FIN ? (Y0 - 5) : (Y0 - 4);
    s.ownN = ld4(sp, rs, c0);
    s.extN = isEdge ? ld4(sp, rs, ecc) : make_float4(0.f, 0.f, 0.f, 0.f);

    int r = rs;
    #pragma unroll 1
    for (int it = 0; it < NOUT; ++it) {
        step_gen<0, FIN>(s, sp, dp, r + 0, lane, c0, ecc, Y0, CFIRST, writeok, isEdge, cv, dup, kC1, kC3, kM7, kM1);
        step_gen<1, FIN>(s, sp, dp, r + 1, lane, c0, ecc, Y0, CFIRST, writeok, isEdge, cv, dup, kC1, kC3, kM7, kM1);
        step_gen<2, FIN>(s, sp, dp, r + 2, lane, c0, ecc, Y0, CFIRST, writeok, isEdge, cv, dup, kC1, kC3, kM7, kM1);
        step_gen<3, FIN>(s, sp, dp, r + 3, lane, c0, ecc, Y0, CFIRST, writeok, isEdge, cv, dup, kC1, kC3, kM7, kM1);
        step_gen<4, FIN>(s, sp, dp, r + 4, lane, c0, ecc, Y0, CFIRST, writeok, isEdge, cv, dup, kC1, kC3, kM7, kM1);
        step_gen<5, FIN>(s, sp, dp, r + 5, lane, c0, ecc, Y0, CFIRST, writeok, isEdge, cv, dup, kC1, kC3, kM7, kM1);
        step_gen<6, FIN>(s, sp, dp, r + 6, lane, c0, ecc, Y0, CFIRST, writeok, isEdge, cv, dup, kC1, kC3, kM7, kM1);
        r += 7;
    }
}

extern "C" void kernel_launch(void* const* d_in, const int* in_sizes, int n_in,
                              void* d_out, int out_size)
{
    const float* x = (const float*)d_in[0];
    float* out = (float*)d_out;

    float *A, *B;
    cudaGetSymbolAddress((void**)&A, g_bufA);
    cudaGetSymbolAddress((void**)&B, g_bufB);

    dim3 gi(7, 30, NB);
    dim3 ge(9, HH / TH, NB);
    int dup = (out_size >= 2 * NPIX) ? 1 : 0;

    sweep_int<false><<<gi, 32>>>(x, A, 0);
    sweep_edge<false><<<ge, 32>>>(x, A, 0);
    sweep_int<false><<<gi, 32>>>(A, B, 0);
    sweep_edge<false><<<ge, 32>>>(A, B, 0);
    sweep_int<false><<<gi, 32>>>(B, A, 0);
    sweep_edge<false><<<ge, 32>>>(B, A, 0);
    sweep_int<true ><<<gi, 32>>>(A, out, dup);
    sweep_edge<true ><<<ge, 32>>>(A, out, dup);
}

// round 7
// speedup vs baseline: 1.2100x; 1.2100x over previous
#include <cuda_runtime.h>
#include <math_constants.h>

#define HH 1024
#define WW 1024
#define NB 16
#define NPIX (NB * HH * WW)
#define TH 32
#define NOUT 6
#define FULLM 0xffffffffu

__device__ __align__(256) float g_bufA[NPIX];
__device__ __align__(256) float g_bufB[NPIX];

#define C1 (1.0f / 24.0f)
#define C3 (3.0f / 24.0f)
#define C7 (7.0f / 24.0f)
#define NEGINF (-CUDART_INF_F)

typedef unsigned long long u64;

#define PK2(d, lo, hi)  asm("mov.b64 %0, {%1, %2};" : "=l"(d) : "f"(lo), "f"(hi))
#define UPK2(lo, hi, s) asm("mov.b64 {%0, %1}, %2;" : "=f"(lo), "=f"(hi) : "l"(s))
#define ADD2(d, a, b)   asm("add.rn.f32x2 %0, %1, %2;" : "=l"(d) : "l"(a), "l"(b))
#define ACC2(d, b)      asm("add.rn.f32x2 %0, %0, %1;" : "+l"(d) : "l"(b))
#define MUL2(d, a, b)   asm("mul.rn.f32x2 %0, %1, %2;" : "=l"(d) : "l"(a), "l"(b))
#define FMA2(d, a, b, c) asm("fma.rn.f32x2 %0, %1, %2, %3;" : "=l"(d) : "l"(a), "l"(b), "l"(c))

// ---- packed filter + ring accumulate; returns completed slot in raw[4] ----
template<int U>
__device__ __forceinline__ void filt(const float w[10], u64 a[7][2],
                                     u64 kC1, u64 kC3, u64 kM7, u64 kM1,
                                     float raw[4])
{
    u64 P[9];
    #pragma unroll
    for (int j = 0; j < 9; ++j) PK2(P[j], w[j], w[j + 1]);

    #pragma unroll
    for (int p = 0; p < 2; ++p) {
        const int o = 2 * p;
        u64 t1, Pt, Puu, Pvv, Px2;
        ADD2(t1, P[2 + o], P[3 + o]);
        ADD2(Pt, t1, P[4 + o]);
        ADD2(Puu, P[1 + o], P[5 + o]);
        ADD2(Pvv, P[0 + o], P[6 + o]);
        ADD2(Px2, P[2 + o], P[4 + o]);

        u64 hA, hB, hC, hD, m1, m2, m3, i1, i2, i3;
        MUL2(hA, kC1, Pt);
        MUL2(m1, kC1, Puu);
        FMA2(hB, kC3, Pt, m1);
        MUL2(m2, kC1, P[0 + o]);
        FMA2(i1, kM7, P[3 + o], m2);
        FMA2(hC, kC3, Puu, i1);
        MUL2(m3, kC1, Pvv);
        FMA2(i2, kM7, Px2, m3);
        FMA2(i3, kC3, Puu, i2);
        FMA2(hD, kM1, P[3 + o], i3);

        ACC2(a[(U + 0) % 7][p], hA);
        ACC2(a[(U + 1) % 7][p], hB);
        ACC2(a[(U + 2) % 7][p], hC);
        ACC2(a[(U + 3) % 7][p], hD);
        ACC2(a[(U + 4) % 7][p], hC);
        ACC2(a[(U + 5) % 7][p], hB);
        ACC2(a[(U + 6) % 7][p], hA);
    }
    UPK2(raw[0], raw[1], a[U % 7][0]);
    UPK2(raw[2], raw[3], a[U % 7][1]);
    a[U % 7][0] = 0ull;
    a[U % 7][1] = 0ull;
}

// ===================== INTERIOR path: 3-LDG window, no shuffles in filter ====
struct StI {
    u64 a[7][2];
    float4 L, M, R;     // prefetched next row (cols c0-4.., c0.., c0+4..)
    float cp[4], pm[4];
    int bpp1, bpp2;     // FIN: byte-packed bit history
};

template<int U, bool FIN, bool VM, bool WR>
__device__ __forceinline__ void step_int(StI& s, const float*& p0, float*& wp,
                                         bool writeok, int dup,
                                         u64 kC1, u64 kC3, u64 kM7, u64 kM1)
{
    float w[10] = { s.L.y, s.L.z, s.L.w, s.M.x, s.M.y, s.M.z, s.M.w,
                    s.R.x, s.R.y, s.R.z };
    s.L = *reinterpret_cast<const float4*>(p0 - 4);
    s.M = *reinterpret_cast<const float4*>(p0);
    s.R = *reinterpret_cast<const float4*>(p0 + 4);
    p0 += WW;

    float raw[4];
    filt<U>(w, s.a, kC1, kC3, kM7, kM1, raw);

    if (VM) {
        float vm[4];
        #pragma unroll
        for (int k = 0; k < 4; ++k) {
            vm[k]  = fmaxf(s.pm[k], raw[k]);
            s.pm[k] = fmaxf(raw[k], s.cp[k]);
            s.cp[k] = raw[k];
        }
        float vmL = __shfl_up_sync(FULLM, vm[3], 1);
        float vmR = __shfl_down_sync(FULLM, vm[0], 1);
        float m0 = fmaxf(vmL,   fmaxf(vm[0], vm[1]));
        float m1 = fmaxf(vm[0], fmaxf(vm[1], vm[2]));
        float m2 = fmaxf(vm[1], fmaxf(vm[2], vm[3]));
        float m3 = fmaxf(vm[2], fmaxf(vm[3], vmR));

        if (!FIN) {
            if (WR && writeok)
                *reinterpret_cast<float4*>(wp) = make_float4(m0, m1, m2, m3);
        } else {
            int bp = (m0 > 0.5f ? 1 : 0) | ((m1 > 0.5f ? 1 : 0) << 8)
                   | ((m2 > 0.5f ? 1 : 0) << 16) | ((m3 > 0.5f ? 1 : 0) << 24);
            int sp_ = s.bpp2 + s.bpp1 + bp;     // per-byte counts <= 3, carry-free
            s.bpp2 = s.bpp1; s.bpp1 = bp;
            int sLp = __shfl_up_sync(FULLM, sp_, 1);
            int sRp = __shfl_down_sync(FULLM, sp_, 1);
            if (WR && writeok) {
                unsigned u = (unsigned)sp_;
                int s0 = u & 0xFF, s1 = (u >> 8) & 0xFF,
                    s2 = (u >> 16) & 0xFF, s3 = u >> 24;
                int n0 = (int)(((unsigned)sLp) >> 24) + s0 + s1;
                int n1 = s0 + s1 + s2;
                int n2 = s1 + s2 + s3;
                int n3 = s2 + s3 + (sRp & 0xFF);
                float4 o = make_float4(n0 >= 8 ? 1.f : 0.f, n1 >= 8 ? 1.f : 0.f,
                                       n2 >= 8 ? 1.f : 0.f, n3 >= 8 ? 1.f : 0.f);
                *reinterpret_cast<float4*>(wp) = o;
                if (dup) *reinterpret_cast<float4*>(wp + NPIX) = o;
            }
        }
        wp += WW;
    }
}

template<bool FIN>
__device__ __forceinline__ void run_int(const float* sp, float* dp, int c0, int Y0,
                                        int lane, int dup,
                                        u64 kC1, u64 kC3, u64 kM7, u64 kM1)
{
    const bool writeok = (lane >= 1) && (lane <= 30);

    StI s;
    #pragma unroll
    for (int i = 0; i < 7; ++i) { s.a[i][0] = 0ull; s.a[i][1] = 0ull; }
    #pragma unroll
    for (int k = 0; k < 4; ++k) { s.cp[k] = NEGINF; s.pm[k] = NEGINF; }
    s.bpp1 = 0; s.bpp2 = 0;

    const int rs = FIN ? (Y0 - 5) : (Y0 - 4);
    const float* pr = sp + (size_t)rs * WW + c0;
    s.L = *reinterpret_cast<const float4*>(pr - 4);
    s.M = *reinterpret_cast<const float4*>(pr);
    s.R = *reinterpret_cast<const float4*>(pr + 4);

    const float* p0 = pr + WW;
    float* wp = dp + (size_t)(FIN ? (Y0 - 4) : (Y0 - 2)) * WW + c0;

    #define SI(UU, VMf, WRf) \
        step_int<UU, FIN, VMf, WRf>(s, p0, wp, writeok, dup, kC1, kC3, kM7, kM1);

    if (!FIN) {
        SI(0,false,false) SI(1,false,false) SI(2,false,false)
        SI(3,false,false) SI(4,false,false) SI(5,false,false)
        SI(6,true,false)  SI(0,true,false)
        #pragma unroll 1
        for (int g = 0; g < 4; ++g) {
            SI(1,true,true) SI(2,true,true) SI(3,true,true) SI(4,true,true)
            SI(5,true,true) SI(6,true,true) SI(0,true,true)
        }
        SI(1,true,true) SI(2,true,true) SI(3,true,true) SI(4,true,true)
    } else {
        SI(0,false,false) SI(1,false,false) SI(2,false,false)
        SI(3,false,false) SI(4,false,false) SI(5,false,false)
        SI(6,true,false)  SI(0,true,false) SI(1,true,false) SI(2,true,false)
        #pragma unroll 1
        for (int g = 0; g < 4; ++g) {
            SI(3,true,true) SI(4,true,true) SI(5,true,true) SI(6,true,true)
            SI(0,true,true) SI(1,true,true) SI(2,true,true)
        }
        SI(3,true,true) SI(4,true,true) SI(5,true,true) SI(6,true,true)
    }
    #undef SI
}

// ===================== GENERIC path (full runtime guards) =====================
struct StG {
    u64 a[7][2];
    float4 ownN, extN;
    float cp[4], pm[4];
    int bp1[4], bp2[4];
};

__device__ __forceinline__ float4 ld4(const float* __restrict__ p, int r, int cc) {
    if ((unsigned)r < (unsigned)HH && (unsigned)cc < (unsigned)WW)
        return *reinterpret_cast<const float4*>(p + (size_t)r * WW + cc);
    return make_float4(0.f, 0.f, 0.f, 0.f);
}

template<int U, bool FIN>
__device__ __forceinline__ void step_gen(StG& s, const float* sp, float* dp, int r,
                                         int lane, int c0, int ecc, int Y0, int CFIRST,
                                         bool writeok, bool isEdge, const bool cv[4],
                                         int dup, u64 kC1, u64 kC3, u64 kM7, u64 kM1)
{
    float4 own = s.ownN, ext = s.extN;
    s.ownN = ld4(sp, r + 1, c0);
    s.extN = isEdge ? ld4(sp, r + 1, ecc) : make_float4(0.f, 0.f, 0.f, 0.f);

    float w[10];
    w[3] = own.x; w[4] = own.y; w[5] = own.z; w[6] = own.w;
    w[0] = __shfl_up_sync(FULLM, own.y, 1);
    w[1] = __shfl_up_sync(FULLM, own.z, 1);
    w[2] = __shfl_up_sync(FULLM, own.w, 1);
    w[7] = __shfl_down_sync(FULLM, own.x, 1);
    w[8] = __shfl_down_sync(FULLM, own.y, 1);
    w[9] = __shfl_down_sync(FULLM, own.z, 1);
    if (lane == 0)  { w[0] = ext.y; w[1] = ext.z; w[2] = ext.w; }
    if (lane == 31) { w[7] = ext.x; w[8] = ext.y; w[9] = ext.z; }

    float raw[4];
    filt<U>(w, s.a, kC1, kC3, kM7, kM1, raw);

    const int cr = r - 3;
    if (cr >= CFIRST) {
        const bool rv = (unsigned)cr < (unsigned)HH;
        float cur[4], vm[4];
        #pragma unroll
        for (int k = 0; k < 4; ++k) {
            cur[k] = (rv && cv[k]) ? raw[k] : NEGINF;
            vm[k]  = fmaxf(s.pm[k], cur[k]);
            s.pm[k] = fmaxf(cur[k], s.cp[k]);
            s.cp[k] = cur[k];
        }
        float vmL = __shfl_up_sync(FULLM, vm[3], 1);
        float vmR = __shfl_down_sync(FULLM, vm[0], 1);
        float m0 = fmaxf(vmL,   fmaxf(vm[0], vm[1]));
        float m1 = fmaxf(vm[0], fmaxf(vm[1], vm[2]));
        float m2 = fmaxf(vm[1], fmaxf(vm[2], vm[3]));
        float m3 = fmaxf(vm[2], fmaxf(vm[3], vmR));
        const int v = cr - 1;

        if (!FIN) {
            if (writeok && v >= Y0 && v < Y0 + TH && v < HH)
                *reinterpret_cast<float4*>(dp + (size_t)v * WW + c0)
                    = make_float4(m0, m1, m2, m3);
        } else {
            const bool bv = (unsigned)v < (unsigned)HH;
            int b0 = (bv && cv[0] && m0 > 0.5f) ? 1 : 0;
            int b1 = (bv && cv[1] && m1 > 0.5f) ? 1 : 0;
            int b2 = (bv && cv[2] && m2 > 0.5f) ? 1 : 0;
            int b3 = (bv && cv[3] && m3 > 0.5f) ? 1 : 0;
            int s0 = s.bp2[0] + s.bp1[0] + b0;
            int s1 = s.bp2[1] + s.bp1[1] + b1;
            int s2 = s.bp2[2] + s.bp1[2] + b2;
            int s3 = s.bp2[3] + s.bp1[3] + b3;
            s.bp2[0] = s.bp1[0]; s.bp2[1] = s.bp1[1];
            s.bp2[2] = s.bp1[2]; s.bp2[3] = s.bp1[3];
            s.bp1[0] = b0; s.bp1[1] = b1; s.bp1[2] = b2; s.bp1[3] = b3;
            int sL = __shfl_up_sync(FULLM, s3, 1);
            int sR = __shfl_down_sync(FULLM, s0, 1);
            int n0 = sL + s0 + s1;
            int n1 = s0 + s1 + s2;
            int n2 = s1 + s2 + s3;
            int n3 = s2 + s3 + sR;
            const int wr = v - 1;
            if (writeok && wr >= Y0 && wr < Y0 + TH && (unsigned)wr < (unsigned)HH) {
                float4 o = make_float4(n0 >= 8 ? 1.f : 0.f, n1 >= 8 ? 1.f : 0.f,
                                       n2 >= 8 ? 1.f : 0.f, n3 >= 8 ? 1.f : 0.f);
                float* op = dp + (size_t)wr * WW + c0;
                *reinterpret_cast<float4*>(op) = o;
                if (dup) *reinterpret_cast<float4*>(op + NPIX) = o;
            }
        }
    }
}

template<bool FIN>
__device__ __noinline__ void run_gen(const float* sp, float* dp, int c0, int Y0,
                                     int lane, int dup,
                                     u64 kC1, u64 kC3, u64 kM7, u64 kM1)
{
    const int ecc = (lane == 0) ? (c0 - 4) : (c0 + 4);
    const bool isEdge = (lane == 0) || (lane == 31);
    const bool writeok = (lane >= 1) && (lane <= 30) && (c0 < WW);
    bool cv[4];
    #pragma unroll
    for (int k = 0; k < 4; ++k) cv[k] = (unsigned)(c0 + k) < (unsigned)WW;
    const int CFIRST = FIN ? (Y0 - 2) : (Y0 - 1);

    StG s;
    #pragma unroll
    for (int i = 0; i < 7; ++i) { s.a[i][0] = 0ull; s.a[i][1] = 0ull; }
    #pragma unroll
    for (int k = 0; k < 4; ++k) {
        s.cp[k] = NEGINF; s.pm[k] = NEGINF; s.bp1[k] = 0; s.bp2[k] = 0;
    }
    const int rs = FIN ? (Y0 - 5) : (Y0 - 4);
    s.ownN = ld4(sp, rs, c0);
    s.extN = isEdge ? ld4(sp, rs, ecc) : make_float4(0.f, 0.f, 0.f, 0.f);

    int r = rs;
    #pragma unroll 1
    for (int it = 0; it < NOUT; ++it) {
        step_gen<0, FIN>(s, sp, dp, r + 0, lane, c0, ecc, Y0, CFIRST, writeok, isEdge, cv, dup, kC1, kC3, kM7, kM1);
        step_gen<1, FIN>(s, sp, dp, r + 1, lane, c0, ecc, Y0, CFIRST, writeok, isEdge, cv, dup, kC1, kC3, kM7, kM1);
        step_gen<2, FIN>(s, sp, dp, r + 2, lane, c0, ecc, Y0, CFIRST, writeok, isEdge, cv, dup, kC1, kC3, kM7, kM1);
        step_gen<3, FIN>(s, sp, dp, r + 3, lane, c0, ecc, Y0, CFIRST, writeok, isEdge, cv, dup, kC1, kC3, kM7, kM1);
        step_gen<4, FIN>(s, sp, dp, r + 4, lane, c0, ecc, Y0, CFIRST, writeok, isEdge, cv, dup, kC1, kC3, kM7, kM1);
        step_gen<5, FIN>(s, sp, dp, r + 5, lane, c0, ecc, Y0, CFIRST, writeok, isEdge, cv, dup, kC1, kC3, kM7, kM1);
        step_gen<6, FIN>(s, sp, dp, r + 6, lane, c0, ecc, Y0, CFIRST, writeok, isEdge, cv, dup, kC1, kC3, kM7, kM1);
        r += 7;
    }
}

// ===================== combined kernel =====================
template<bool FIN>
__global__ void __launch_bounds__(32, 24) sweep(const float* __restrict__ src,
                                                float* __restrict__ dst,
                                                int dup)
{
    const int lane = threadIdx.x;
    const int sx = blockIdx.x;
    const int by = blockIdx.y;
    const int b  = blockIdx.z;
    const int Y0 = by * TH;
    const int c0 = 120 * sx - 4 + 4 * lane;
    const float* sp = src + (size_t)b * HH * WW;
    float* dp = dst + (size_t)b * HH * WW;

    u64 kC1, kC3, kM7, kM1;
    PK2(kC1, C1, C1); PK2(kC3, C3, C3); PK2(kM7, -C7, -C7); PK2(kM1, -1.0f, -1.0f);

    if (sx >= 1 && sx <= 7 && by >= 1 && by <= 30)
        run_int<FIN>(sp, dp, c0, Y0, lane, dup, kC1, kC3, kM7, kM1);
    else
        run_gen<FIN>(sp, dp, c0, Y0, lane, dup, kC1, kC3, kM7, kM1);
}

extern "C" void kernel_launch(void* const* d_in, const int* in_sizes, int n_in,
                              void* d_out, int out_size)
{
    const float* x = (const float*)d_in[0];
    float* out = (float*)d_out;

    float *A, *B;
    cudaGetSymbolAddress((void**)&A, g_bufA);
    cudaGetSymbolAddress((void**)&B, g_bufB);

    dim3 grid(9, HH / TH, NB);
    int dup = (out_size >= 2 * NPIX) ? 1 : 0;

    sweep<false><<<grid, 32>>>(x, A, 0);
    sweep<false><<<grid, 32>>>(A, B, 0);
    sweep<false><<<grid, 32>>>(B, A, 0);
    sweep<true ><<<grid, 32>>>(A, out, dup);
}

// round 8
// speedup vs baseline: 1.2258x; 1.0130x over previous
#include <cuda_runtime.h>
#include <math_constants.h>

#define HH 1024
#define WW 1024
#define NB 16
#define NPIX (NB * HH * WW)
#define TH 32
#define NOUT 6
#define FULLM 0xffffffffu

__device__ __align__(256) float g_bufA[NPIX];
__device__ __align__(256) float g_bufB[NPIX];

#define C1 (1.0f / 24.0f)
#define C3 (3.0f / 24.0f)
#define C7 (7.0f / 24.0f)
#define NEGINF (-CUDART_INF_F)

typedef unsigned long long u64;

#define PK2(d, lo, hi)  asm("mov.b64 %0, {%1, %2};" : "=l"(d) : "f"(lo), "f"(hi))
#define UPK2(lo, hi, s) asm("mov.b64 {%0, %1}, %2;" : "=f"(lo), "=f"(hi) : "l"(s))
#define ADD2(d, a, b)   asm("add.rn.f32x2 %0, %1, %2;" : "=l"(d) : "l"(a), "l"(b))
#define ACC2(d, b)      asm("add.rn.f32x2 %0, %0, %1;" : "+l"(d) : "l"(b))
#define MUL2(d, a, b)   asm("mul.rn.f32x2 %0, %1, %2;" : "=l"(d) : "l"(a), "l"(b))
#define FMA2(d, a, b, c) asm("fma.rn.f32x2 %0, %1, %2, %3;" : "=l"(d) : "l"(a), "l"(b), "l"(c))

// ---- packed filter + ring accumulate; returns completed slot in raw[4] ----
template<int U>
__device__ __forceinline__ void filt(const float w[10], u64 a[7][2],
                                     u64 kC1, u64 kC3, u64 kM7, u64 kM1,
                                     float raw[4])
{
    u64 P[9];
    #pragma unroll
    for (int j = 0; j < 9; ++j) PK2(P[j], w[j], w[j + 1]);

    #pragma unroll
    for (int p = 0; p < 2; ++p) {
        const int o = 2 * p;
        u64 t1, Pt, Puu, Pvv, Px2;
        ADD2(t1, P[2 + o], P[3 + o]);
        ADD2(Pt, t1, P[4 + o]);
        ADD2(Puu, P[1 + o], P[5 + o]);
        ADD2(Pvv, P[0 + o], P[6 + o]);
        ADD2(Px2, P[2 + o], P[4 + o]);

        u64 hA, hB, hC, hD, m1, m2, m3, i1, i2, i3;
        MUL2(hA, kC1, Pt);
        MUL2(m1, kC1, Puu);
        FMA2(hB, kC3, Pt, m1);
        MUL2(m2, kC1, P[0 + o]);
        FMA2(i1, kM7, P[3 + o], m2);
        FMA2(hC, kC3, Puu, i1);
        MUL2(m3, kC1, Pvv);
        FMA2(i2, kM7, Px2, m3);
        FMA2(i3, kC3, Puu, i2);
        FMA2(hD, kM1, P[3 + o], i3);

        ACC2(a[(U + 0) % 7][p], hA);
        ACC2(a[(U + 1) % 7][p], hB);
        ACC2(a[(U + 2) % 7][p], hC);
        ACC2(a[(U + 3) % 7][p], hD);
        ACC2(a[(U + 4) % 7][p], hC);
        ACC2(a[(U + 5) % 7][p], hB);
        ACC2(a[(U + 6) % 7][p], hA);
    }
    UPK2(raw[0], raw[1], a[U % 7][0]);
    UPK2(raw[2], raw[3], a[U % 7][1]);
    a[U % 7][0] = 0ull;
    a[U % 7][1] = 0ull;
}

// ============ INTERIOR path: 3-LDG window, depth-2 prefetch pipeline ========
struct StI {
    u64 a[7][2];
    float4 L0, M0, R0;   // row r   (consumed this step)
    float4 L1, M1, R1;   // row r+1 (in flight / arrived)
    float cp[4], pm[4];
    int bpp1, bpp2;      // FIN: byte-packed bit history
};

template<int U, bool FIN, bool VM, bool WR>
__device__ __forceinline__ void step_int(StI& s, const float*& p0, float*& wp,
                                         bool writeok, int dup,
                                         u64 kC1, u64 kC3, u64 kM7, u64 kM1)
{
    float w[10] = { s.L0.y, s.L0.z, s.L0.w, s.M0.x, s.M0.y, s.M0.z, s.M0.w,
                    s.R0.x, s.R0.y, s.R0.z };
    s.L0 = s.L1; s.M0 = s.M1; s.R0 = s.R1;
    s.L1 = *reinterpret_cast<const float4*>(p0 - 4);   // row r+2
    s.M1 = *reinterpret_cast<const float4*>(p0);
    s.R1 = *reinterpret_cast<const float4*>(p0 + 4);
    p0 += WW;

    float raw[4];
    filt<U>(w, s.a, kC1, kC3, kM7, kM1, raw);

    if (VM) {
        float vm[4];
        #pragma unroll
        for (int k = 0; k < 4; ++k) {
            vm[k]  = fmaxf(s.pm[k], raw[k]);
            s.pm[k] = fmaxf(raw[k], s.cp[k]);
            s.cp[k] = raw[k];
        }
        float vmL = __shfl_up_sync(FULLM, vm[3], 1);
        float vmR = __shfl_down_sync(FULLM, vm[0], 1);
        float m0 = fmaxf(vmL,   fmaxf(vm[0], vm[1]));
        float m1 = fmaxf(vm[0], fmaxf(vm[1], vm[2]));
        float m2 = fmaxf(vm[1], fmaxf(vm[2], vm[3]));
        float m3 = fmaxf(vm[2], fmaxf(vm[3], vmR));

        if (!FIN) {
            if (WR && writeok)
                *reinterpret_cast<float4*>(wp) = make_float4(m0, m1, m2, m3);
        } else {
            int bp = (m0 > 0.5f ? 1 : 0) | ((m1 > 0.5f ? 1 : 0) << 8)
                   | ((m2 > 0.5f ? 1 : 0) << 16) | ((m3 > 0.5f ? 1 : 0) << 24);
            int sp_ = s.bpp2 + s.bpp1 + bp;     // per-byte counts <= 3, carry-free
            s.bpp2 = s.bpp1; s.bpp1 = bp;
            int sLp = __shfl_up_sync(FULLM, sp_, 1);
            int sRp = __shfl_down_sync(FULLM, sp_, 1);
            if (WR && writeok) {
                unsigned u = (unsigned)sp_;
                int s0 = u & 0xFF, s1 = (u >> 8) & 0xFF,
                    s2 = (u >> 16) & 0xFF, s3 = u >> 24;
                int n0 = (int)(((unsigned)sLp) >> 24) + s0 + s1;
                int n1 = s0 + s1 + s2;
                int n2 = s1 + s2 + s3;
                int n3 = s2 + s3 + (sRp & 0xFF);
                float4 o = make_float4(n0 >= 8 ? 1.f : 0.f, n1 >= 8 ? 1.f : 0.f,
                                       n2 >= 8 ? 1.f : 0.f, n3 >= 8 ? 1.f : 0.f);
                *reinterpret_cast<float4*>(wp) = o;
                if (dup) *reinterpret_cast<float4*>(wp + NPIX) = o;
            }
        }
        wp += WW;
    }
}

template<bool FIN>
__device__ __forceinline__ void run_int(const float* sp, float* dp, int c0, int Y0,
                                        int lane, int dup,
                                        u64 kC1, u64 kC3, u64 kM7, u64 kM1)
{
    const bool writeok = (lane >= 1) && (lane <= 30);

    StI s;
    #pragma unroll
    for (int i = 0; i < 7; ++i) { s.a[i][0] = 0ull; s.a[i][1] = 0ull; }
    #pragma unroll
    for (int k = 0; k < 4; ++k) { s.cp[k] = NEGINF; s.pm[k] = NEGINF; }
    s.bpp1 = 0; s.bpp2 = 0;

    const int rs = FIN ? (Y0 - 5) : (Y0 - 4);
    const float* pr = sp + (size_t)rs * WW + c0;
    s.L0 = *reinterpret_cast<const float4*>(pr - 4);        // row rs
    s.M0 = *reinterpret_cast<const float4*>(pr);
    s.R0 = *reinterpret_cast<const float4*>(pr + 4);
    s.L1 = *reinterpret_cast<const float4*>(pr + WW - 4);   // row rs+1
    s.M1 = *reinterpret_cast<const float4*>(pr + WW);
    s.R1 = *reinterpret_cast<const float4*>(pr + WW + 4);

    const float* p0 = pr + 2 * WW;    // next load = row rs+2
    float* wp = dp + (size_t)(FIN ? (Y0 - 4) : (Y0 - 2)) * WW + c0;

    #define SI(UU, VMf, WRf) \
        step_int<UU, FIN, VMf, WRf>(s, p0, wp, writeok, dup, kC1, kC3, kM7, kM1);

    if (!FIN) {
        SI(0,false,false) SI(1,false,false) SI(2,false,false)
        SI(3,false,false) SI(4,false,false) SI(5,false,false)
        SI(6,true,false)  SI(0,true,false)
        #pragma unroll 1
        for (int g = 0; g < 2; ++g) {   // 14-step body: even pipeline rotation
            SI(1,true,true) SI(2,true,true) SI(3,true,true) SI(4,true,true)
            SI(5,true,true) SI(6,true,true) SI(0,true,true)
            SI(1,true,true) SI(2,true,true) SI(3,true,true) SI(4,true,true)
            SI(5,true,true) SI(6,true,true) SI(0,true,true)
        }
        SI(1,true,true) SI(2,true,true) SI(3,true,true) SI(4,true,true)
    } else {
        SI(0,false,false) SI(1,false,false) SI(2,false,false)
        SI(3,false,false) SI(4,false,false) SI(5,false,false)
        SI(6,true,false)  SI(0,true,false) SI(1,true,false) SI(2,true,false)
        #pragma unroll 1
        for (int g = 0; g < 2; ++g) {
            SI(3,true,true) SI(4,true,true) SI(5,true,true) SI(6,true,true)
            SI(0,true,true) SI(1,true,true) SI(2,true,true)
            SI(3,true,true) SI(4,true,true) SI(5,true,true) SI(6,true,true)
            SI(0,true,true) SI(1,true,true) SI(2,true,true)
        }
        SI(3,true,true) SI(4,true,true) SI(5,true,true) SI(6,true,true)
    }
    #undef SI
}

// ===================== GENERIC path (full runtime guards) =====================
struct StG {
    u64 a[7][2];
    float4 ownN, extN;
    float cp[4], pm[4];
    int bp1[4], bp2[4];
};

__device__ __forceinline__ float4 ld4(const float* __restrict__ p, int r, int cc) {
    if ((unsigned)r < (unsigned)HH && (unsigned)cc < (unsigned)WW)
        return *reinterpret_cast<const float4*>(p + (size_t)r * WW + cc);
    return make_float4(0.f, 0.f, 0.f, 0.f);
}

template<int U, bool FIN>
__device__ __forceinline__ void step_gen(StG& s, const float* sp, float* dp, int r,
                                         int lane, int c0, int ecc, int Y0, int CFIRST,
                                         bool writeok, bool isEdge, const bool cv[4],
                                         int dup, u64 kC1, u64 kC3, u64 kM7, u64 kM1)
{
    float4 own = s.ownN, ext = s.extN;
    s.ownN = ld4(sp, r + 1, c0);
    s.extN = isEdge ? ld4(sp, r + 1, ecc) : make_float4(0.f, 0.f, 0.f, 0.f);

    float w[10];
    w[3] = own.x; w[4] = own.y; w[5] = own.z; w[6] = own.w;
    w[0] = __shfl_up_sync(FULLM, own.y, 1);
    w[1] = __shfl_up_sync(FULLM, own.z, 1);
    w[2] = __shfl_up_sync(FULLM, own.w, 1);
    w[7] = __shfl_down_sync(FULLM, own.x, 1);
    w[8] = __shfl_down_sync(FULLM, own.y, 1);
    w[9] = __shfl_down_sync(FULLM, own.z, 1);
    if (lane == 0)  { w[0] = ext.y; w[1] = ext.z; w[2] = ext.w; }
    if (lane == 31) { w[7] = ext.x; w[8] = ext.y; w[9] = ext.z; }

    float raw[4];
    filt<U>(w, s.a, kC1, kC3, kM7, kM1, raw);

    const int cr = r - 3;
    if (cr >= CFIRST) {
        const bool rv = (unsigned)cr < (unsigned)HH;
        float cur[4], vm[4];
        #pragma unroll
        for (int k = 0; k < 4; ++k) {
            cur[k] = (rv && cv[k]) ? raw[k] : NEGINF;
            vm[k]  = fmaxf(s.pm[k], cur[k]);
            s.pm[k] = fmaxf(cur[k], s.cp[k]);
            s.cp[k] = cur[k];
        }
        float vmL = __shfl_up_sync(FULLM, vm[3], 1);
        float vmR = __shfl_down_sync(FULLM, vm[0], 1);
        float m0 = fmaxf(vmL,   fmaxf(vm[0], vm[1]));
        float m1 = fmaxf(vm[0], fmaxf(vm[1], vm[2]));
        float m2 = fmaxf(vm[1], fmaxf(vm[2], vm[3]));
        float m3 = fmaxf(vm[2], fmaxf(vm[3], vmR));
        const int v = cr - 1;

        if (!FIN) {
            if (writeok && v >= Y0 && v < Y0 + TH && v < HH)
                *reinterpret_cast<float4*>(dp + (size_t)v * WW + c0)
                    = make_float4(m0, m1, m2, m3);
        } else {
            const bool bv = (unsigned)v < (unsigned)HH;
            int b0 = (bv && cv[0] && m0 > 0.5f) ? 1 : 0;
            int b1 = (bv && cv[1] && m1 > 0.5f) ? 1 : 0;
            int b2 = (bv && cv[2] && m2 > 0.5f) ? 1 : 0;
            int b3 = (bv && cv[3] && m3 > 0.5f) ? 1 : 0;
            int s0 = s.bp2[0] + s.bp1[0] + b0;
            int s1 = s.bp2[1] + s.bp1[1] + b1;
            int s2 = s.bp2[2] + s.bp1[2] + b2;
            int s3 = s.bp2[3] + s.bp1[3] + b3;
            s.bp2[0] = s.bp1[0]; s.bp2[1] = s.bp1[1];
            s.bp2[2] = s.bp1[2]; s.bp2[3] = s.bp1[3];
            s.bp1[0] = b0; s.bp1[1] = b1; s.bp1[2] = b2; s.bp1[3] = b3;
            int sL = __shfl_up_sync(FULLM, s3, 1);
            int sR = __shfl_down_sync(FULLM, s0, 1);
            int n0 = sL + s0 + s1;
            int n1 = s0 + s1 + s2;
            int n2 = s1 + s2 + s3;
            int n3 = s2 + s3 + sR;
            const int wr = v - 1;
            if (writeok && wr >= Y0 && wr < Y0 + TH && (unsigned)wr < (unsigned)HH) {
                float4 o = make_float4(n0 >= 8 ? 1.f : 0.f, n1 >= 8 ? 1.f : 0.f,
                                       n2 >= 8 ? 1.f : 0.f, n3 >= 8 ? 1.f : 0.f);
                float* op = dp + (size_t)wr * WW + c0;
                *reinterpret_cast<float4*>(op) = o;
                if (dup) *reinterpret_cast<float4*>(op + NPIX) = o;
            }
        }
    }
}

template<bool FIN>
__device__ __noinline__ void run_gen(const float* sp, float* dp, int c0, int Y0,
                                     int lane, int dup,
                                     u64 kC1, u64 kC3, u64 kM7, u64 kM1)
{
    const int ecc = (lane == 0) ? (c0 - 4) : (c0 + 4);
    const bool isEdge = (lane == 0) || (lane == 31);
    const bool writeok = (lane >= 1) && (lane <= 30) && (c0 < WW);
    bool cv[4];
    #pragma unroll
    for (int k = 0; k < 4; ++k) cv[k] = (unsigned)(c0 + k) < (unsigned)WW;
    const int CFIRST = FIN ? (Y0 - 2) : (Y0 - 1);

    StG s;
    #pragma unroll
    for (int i = 0; i < 7; ++i) { s.a[i][0] = 0ull; s.a[i][1] = 0ull; }
    #pragma unroll
    for (int k = 0; k < 4; ++k) {
        s.cp[k] = NEGINF; s.pm[k] = NEGINF; s.bp1[k] = 0; s.bp2[k] = 0;
    }
    const int rs = FIN ? (Y0 - 5) : (Y0 - 4);
    s.ownN = ld4(sp, rs, c0);
    s.extN = isEdge ? ld4(sp, rs, ecc) : make_float4(0.f, 0.f, 0.f, 0.f);

    int r = rs;
    #pragma unroll 1
    for (int it = 0; it < NOUT; ++it) {
        step_gen<0, FIN>(s, sp, dp, r + 0, lane, c0, ecc, Y0, CFIRST, writeok, isEdge, cv, dup, kC1, kC3, kM7, kM1);
        step_gen<1, FIN>(s, sp, dp, r + 1, lane, c0, ecc, Y0, CFIRST, writeok, isEdge, cv, dup, kC1, kC3, kM7, kM1);
        step_gen<2, FIN>(s, sp, dp, r + 2, lane, c0, ecc, Y0, CFIRST, writeok, isEdge, cv, dup, kC1, kC3, kM7, kM1);
        step_gen<3, FIN>(s, sp, dp, r + 3, lane, c0, ecc, Y0, CFIRST, writeok, isEdge, cv, dup, kC1, kC3, kM7, kM1);
        step_gen<4, FIN>(s, sp, dp, r + 4, lane, c0, ecc, Y0, CFIRST, writeok, isEdge, cv, dup, kC1, kC3, kM7, kM1);
        step_gen<5, FIN>(s, sp, dp, r + 5, lane, c0, ecc, Y0, CFIRST, writeok, isEdge, cv, dup, kC1, kC3, kM7, kM1);
        step_gen<6, FIN>(s, sp, dp, r + 6, lane, c0, ecc, Y0, CFIRST, writeok, isEdge, cv, dup, kC1, kC3, kM7, kM1);
        r += 7;
    }
}

// ===================== combined kernel =====================
template<bool FIN>
__global__ void __launch_bounds__(32, 20) sweep(const float* __restrict__ src,
                                                float* __restrict__ dst,
                                                int dup)
{
    const int lane = threadIdx.x;
    const int sx = blockIdx.x;
    const int by = blockIdx.y;
    const int b  = blockIdx.z;
    const int Y0 = by * TH;
    const int c0 = 120 * sx - 4 + 4 * lane;
    const float* sp = src + (size_t)b * HH * WW;
    float* dp = dst + (size_t)b * HH * WW;

    u64 kC1, kC3, kM7, kM1;
    PK2(kC1, C1, C1); PK2(kC3, C3, C3); PK2(kM7, -C7, -C7); PK2(kM1, -1.0f, -1.0f);

    if (sx >= 1 && sx <= 7 && by >= 1 && by <= 30)
        run_int<FIN>(sp, dp, c0, Y0, lane, dup, kC1, kC3, kM7, kM1);
    else
        run_gen<FIN>(sp, dp, c0, Y0, lane, dup, kC1, kC3, kM7, kM1);
}

extern "C" void kernel_launch(void* const* d_in, const int* in_sizes, int n_in,
                              void* d_out, int out_size)
{
    const float* x = (const float*)d_in[0];
    float* out = (float*)d_out;

    float *A, *B;
    cudaGetSymbolAddress((void**)&A, g_bufA);
    cudaGetSymbolAddress((void**)&B, g_bufB);

    dim3 grid(9, HH / TH, NB);
    int dup = (out_size >= 2 * NPIX) ? 1 : 0;

    sweep<false><<<grid, 32>>>(x, A, 0);
    sweep<false><<<grid, 32>>>(A, B, 0);
    sweep<false><<<grid, 32>>>(B, A, 0);
    sweep<true ><<<grid, 32>>>(A, out, dup);
}

// round 9
// speedup vs baseline: 1.2375x; 1.0096x over previous
#include <cuda_runtime.h>
#include <math_constants.h>

#define HH 1024
#define WW 1024
#define NB 16
#define NPIX (NB * HH * WW)
#define TH 32
#define NOUT 6
#define FULLM 0xffffffffu

__device__ __align__(256) float g_bufA[NPIX];
__device__ __align__(256) float g_bufB[NPIX];

#define C1 (1.0f / 24.0f)
#define C3 (3.0f / 24.0f)
#define C7 (7.0f / 24.0f)
#define NEGINF (-CUDART_INF_F)

typedef unsigned long long u64;

#define PK2(d, lo, hi)  asm("mov.b64 %0, {%1, %2};" : "=l"(d) : "f"(lo), "f"(hi))
#define UPK2(lo, hi, s) asm("mov.b64 {%0, %1}, %2;" : "=f"(lo), "=f"(hi) : "l"(s))
#define ADD2(d, a, b)   asm("add.rn.f32x2 %0, %1, %2;" : "=l"(d) : "l"(a), "l"(b))
#define ACC2(d, b)      asm("add.rn.f32x2 %0, %0, %1;" : "+l"(d) : "l"(b))
#define MUL2(d, a, b)   asm("mul.rn.f32x2 %0, %1, %2;" : "=l"(d) : "l"(a), "l"(b))
#define FMA2(d, a, b, c) asm("fma.rn.f32x2 %0, %1, %2, %3;" : "=l"(d) : "l"(a), "l"(b), "l"(c))

// ---- packed filter + ring accumulate; returns completed slot in raw[4] ----
template<int U>
__device__ __forceinline__ void filt(const float w[10], u64 a[7][2],
                                     u64 kC1, u64 kC3, u64 kM7, u64 kM1,
                                     float raw[4])
{
    u64 P[9];
    #pragma unroll
    for (int j = 0; j < 9; ++j) PK2(P[j], w[j], w[j + 1]);

    #pragma unroll
    for (int p = 0; p < 2; ++p) {
        const int o = 2 * p;
        u64 t1, Pt, Puu, Pvv, Px2;
        ADD2(t1, P[2 + o], P[3 + o]);
        ADD2(Pt, t1, P[4 + o]);
        ADD2(Puu, P[1 + o], P[5 + o]);
        ADD2(Pvv, P[0 + o], P[6 + o]);
        ADD2(Px2, P[2 + o], P[4 + o]);

        u64 hA, hB, hC, hD, m1, m2, m3, i1, i2, i3;
        MUL2(hA, kC1, Pt);
        MUL2(m1, kC1, Puu);
        FMA2(hB, kC3, Pt, m1);
        MUL2(m2, kC1, P[0 + o]);
        FMA2(i1, kM7, P[3 + o], m2);
        FMA2(hC, kC3, Puu, i1);
        MUL2(m3, kC1, Pvv);
        FMA2(i2, kM7, Px2, m3);
        FMA2(i3, kC3, Puu, i2);
        FMA2(hD, kM1, P[3 + o], i3);

        ACC2(a[(U + 0) % 7][p], hA);
        ACC2(a[(U + 1) % 7][p], hB);
        ACC2(a[(U + 2) % 7][p], hC);
        ACC2(a[(U + 3) % 7][p], hD);
        ACC2(a[(U + 4) % 7][p], hC);
        ACC2(a[(U + 5) % 7][p], hB);
        ACC2(a[(U + 6) % 7][p], hA);
    }
    UPK2(raw[0], raw[1], a[U % 7][0]);
    UPK2(raw[2], raw[3], a[U % 7][1]);
    a[U % 7][0] = 0ull;
    a[U % 7][1] = 0ull;
}

// ======= INTERIOR path: 3-LDG window, bank ping-pong (true depth-2) =========
struct StI {
    u64 a[7][2];
    float cp[4], pm[4];
    int bpp1, bpp2;      // FIN: byte-packed bit history
};

template<int U, bool FIN, bool VM, bool WR>
__device__ __forceinline__ void step_int(StI& s,
                                         float4& L, float4& M, float4& R,
                                         const float*& p0, float*& wp,
                                         bool writeok, int dup,
                                         u64 kC1, u64 kC3, u64 kM7, u64 kM1)
{
    // consume this bank (loaded 2 steps ago), then refill it with row r+2
    float w[10] = { L.y, L.z, L.w, M.x, M.y, M.z, M.w, R.x, R.y, R.z };
    L = *reinterpret_cast<const float4*>(p0 - 4);
    M = *reinterpret_cast<const float4*>(p0);
    R = *reinterpret_cast<const float4*>(p0 + 4);
    p0 += WW;

    float raw[4];
    filt<U>(w, s.a, kC1, kC3, kM7, kM1, raw);

    if (VM) {
        float vm[4];
        #pragma unroll
        for (int k = 0; k < 4; ++k) {
            vm[k]  = fmaxf(s.pm[k], raw[k]);
            s.pm[k] = fmaxf(raw[k], s.cp[k]);
            s.cp[k] = raw[k];
        }
        float vmL = __shfl_up_sync(FULLM, vm[3], 1);
        float vmR = __shfl_down_sync(FULLM, vm[0], 1);
        float m0 = fmaxf(vmL,   fmaxf(vm[0], vm[1]));
        float m1 = fmaxf(vm[0], fmaxf(vm[1], vm[2]));
        float m2 = fmaxf(vm[1], fmaxf(vm[2], vm[3]));
        float m3 = fmaxf(vm[2], fmaxf(vm[3], vmR));

        if (!FIN) {
            if (WR && writeok)
                *reinterpret_cast<float4*>(wp) = make_float4(m0, m1, m2, m3);
        } else {
            int bp = (m0 > 0.5f ? 1 : 0) | ((m1 > 0.5f ? 1 : 0) << 8)
                   | ((m2 > 0.5f ? 1 : 0) << 16) | ((m3 > 0.5f ? 1 : 0) << 24);
            int sp_ = s.bpp2 + s.bpp1 + bp;     // per-byte counts <= 3, carry-free
            s.bpp2 = s.bpp1; s.bpp1 = bp;
            int sLp = __shfl_up_sync(FULLM, sp_, 1);
            int sRp = __shfl_down_sync(FULLM, sp_, 1);
            if (WR && writeok) {
                unsigned u = (unsigned)sp_;
                int s0 = u & 0xFF, s1 = (u >> 8) & 0xFF,
                    s2 = (u >> 16) & 0xFF, s3 = u >> 24;
                int n0 = (int)(((unsigned)sLp) >> 24) + s0 + s1;
                int n1 = s0 + s1 + s2;
                int n2 = s1 + s2 + s3;
                int n3 = s2 + s3 + (sRp & 0xFF);
                float4 o = make_float4(n0 >= 8 ? 1.f : 0.f, n1 >= 8 ? 1.f : 0.f,
                                       n2 >= 8 ? 1.f : 0.f, n3 >= 8 ? 1.f : 0.f);
                *reinterpret_cast<float4*>(wp) = o;
                if (dup) *reinterpret_cast<float4*>(wp + NPIX) = o;
            }
        }
        wp += WW;
    }
}

template<bool FIN>
__device__ __forceinline__ void run_int(const float* sp, float* dp, int c0, int Y0,
                                        int lane, int dup,
                                        u64 kC1, u64 kC3, u64 kM7, u64 kM1)
{
    const bool writeok = (lane >= 1) && (lane <= 30);

    StI s;
    #pragma unroll
    for (int i = 0; i < 7; ++i) { s.a[i][0] = 0ull; s.a[i][1] = 0ull; }
    #pragma unroll
    for (int k = 0; k < 4; ++k) { s.cp[k] = NEGINF; s.pm[k] = NEGINF; }
    s.bpp1 = 0; s.bpp2 = 0;

    const int rs = FIN ? (Y0 - 5) : (Y0 - 4);
    const float* pr = sp + (size_t)rs * WW + c0;
    float4 LA = *reinterpret_cast<const float4*>(pr - 4);        // row rs  (bank A)
    float4 MA = *reinterpret_cast<const float4*>(pr);
    float4 RA = *reinterpret_cast<const float4*>(pr + 4);
    float4 LB = *reinterpret_cast<const float4*>(pr + WW - 4);   // row rs+1 (bank B)
    float4 MB = *reinterpret_cast<const float4*>(pr + WW);
    float4 RB = *reinterpret_cast<const float4*>(pr + WW + 4);

    const float* p0 = pr + 2 * WW;    // next load = row rs+2
    float* wp = dp + (size_t)(FIN ? (Y0 - 4) : (Y0 - 2)) * WW + c0;

    #define SIA(UU, VMf, WRf) \
        step_int<UU, FIN, VMf, WRf>(s, LA, MA, RA, p0, wp, writeok, dup, kC1, kC3, kM7, kM1);
    #define SIB(UU, VMf, WRf) \
        step_int<UU, FIN, VMf, WRf>(s, LB, MB, RB, p0, wp, writeok, dup, kC1, kC3, kM7, kM1);

    if (!FIN) {
        // 8 warm-up (even) -> bank parity consistent at loop entry
        SIA(0,false,false) SIB(1,false,false) SIA(2,false,false) SIB(3,false,false)
        SIA(4,false,false) SIB(5,false,false) SIA(6,true,false)  SIB(0,true,false)
        #pragma unroll 1
        for (int g = 0; g < 2; ++g) {   // 14-step body (even)
            SIA(1,true,true) SIB(2,true,true) SIA(3,true,true) SIB(4,true,true)
            SIA(5,true,true) SIB(6,true,true) SIA(0,true,true)
            SIB(1,true,true) SIA(2,true,true) SIB(3,true,true) SIA(4,true,true)
            SIB(5,true,true) SIA(6,true,true) SIB(0,true,true)
        }
        SIA(1,true,true) SIB(2,true,true) SIA(3,true,true) SIB(4,true,true)
    } else {
        // 10 warm-up (even)
        SIA(0,false,false) SIB(1,false,false) SIA(2,false,false) SIB(3,false,false)
        SIA(4,false,false) SIB(5,false,false) SIA(6,true,false)  SIB(0,true,false)
        SIA(1,true,false)  SIB(2,true,false)
        #pragma unroll 1
        for (int g = 0; g < 2; ++g) {   // 14-step body (even)
            SIA(3,true,true) SIB(4,true,true) SIA(5,true,true) SIB(6,true,true)
            SIA(0,true,true) SIB(1,true,true) SIA(2,true,true)
            SIB(3,true,true) SIA(4,true,true) SIB(5,true,true) SIA(6,true,true)
            SIB(0,true,true) SIA(1,true,true) SIB(2,true,true)
        }
        SIA(3,true,true) SIB(4,true,true) SIA(5,true,true) SIB(6,true,true)
    }
    #undef SIA
    #undef SIB
}

// ===================== GENERIC path (full runtime guards) =====================
struct StG {
    u64 a[7][2];
    float4 ownN, extN;
    float cp[4], pm[4];
    int bp1[4], bp2[4];
};

__device__ __forceinline__ float4 ld4(const float* __restrict__ p, int r, int cc) {
    if ((unsigned)r < (unsigned)HH && (unsigned)cc < (unsigned)WW)
        return *reinterpret_cast<const float4*>(p + (size_t)r * WW + cc);
    return make_float4(0.f, 0.f, 0.f, 0.f);
}

template<int U, bool FIN>
__device__ __forceinline__ void step_gen(StG& s, const float* sp, float* dp, int r,
                                         int lane, int c0, int ecc, int Y0, int CFIRST,
                                         bool writeok, bool isEdge, const bool cv[4],
                                         int dup, u64 kC1, u64 kC3, u64 kM7, u64 kM1)
{
    float4 own = s.ownN, ext = s.extN;
    s.ownN = ld4(sp, r + 1, c0);
    s.extN = isEdge ? ld4(sp, r + 1, ecc) : make_float4(0.f, 0.f, 0.f, 0.f);

    float w[10];
    w[3] = own.x; w[4] = own.y; w[5] = own.z; w[6] = own.w;
    w[0] = __shfl_up_sync(FULLM, own.y, 1);
    w[1] = __shfl_up_sync(FULLM, own.z, 1);
    w[2] = __shfl_up_sync(FULLM, own.w, 1);
    w[7] = __shfl_down_sync(FULLM, own.x, 1);
    w[8] = __shfl_down_sync(FULLM, own.y, 1);
    w[9] = __shfl_down_sync(FULLM, own.z, 1);
    if (lane == 0)  { w[0] = ext.y; w[1] = ext.z; w[2] = ext.w; }
    if (lane == 31) { w[7] = ext.x; w[8] = ext.y; w[9] = ext.z; }

    float raw[4];
    filt<U>(w, s.a, kC1, kC3, kM7, kM1, raw);

    const int cr = r - 3;
    if (cr >= CFIRST) {
        const bool rv = (unsigned)cr < (unsigned)HH;
        float cur[4], vm[4];
        #pragma unroll
        for (int k = 0; k < 4; ++k) {
            cur[k] = (rv && cv[k]) ? raw[k] : NEGINF;
            vm[k]  = fmaxf(s.pm[k], cur[k]);
            s.pm[k] = fmaxf(cur[k], s.cp[k]);
            s.cp[k] = cur[k];
        }
        float vmL = __shfl_up_sync(FULLM, vm[3], 1);
        float vmR = __shfl_down_sync(FULLM, vm[0], 1);
        float m0 = fmaxf(vmL,   fmaxf(vm[0], vm[1]));
        float m1 = fmaxf(vm[0], fmaxf(vm[1], vm[2]));
        float m2 = fmaxf(vm[1], fmaxf(vm[2], vm[3]));
        float m3 = fmaxf(vm[2], fmaxf(vm[3], vmR));
        const int v = cr - 1;

        if (!FIN) {
            if (writeok && v >= Y0 && v < Y0 + TH && v < HH)
                *reinterpret_cast<float4*>(dp + (size_t)v * WW + c0)
                    = make_float4(m0, m1, m2, m3);
        } else {
            const bool bv = (unsigned)v < (unsigned)HH;
            int b0 = (bv && cv[0] && m0 > 0.5f) ? 1 : 0;
            int b1 = (bv && cv[1] && m1 > 0.5f) ? 1 : 0;
            int b2 = (bv && cv[2] && m2 > 0.5f) ? 1 : 0;
            int b3 = (bv && cv[3] && m3 > 0.5f) ? 1 : 0;
            int s0 = s.bp2[0] + s.bp1[0] + b0;
            int s1 = s.bp2[1] + s.bp1[1] + b1;
            int s2 = s.bp2[2] + s.bp1[2] + b2;
            int s3 = s.bp2[3] + s.bp1[3] + b3;
            s.bp2[0] = s.bp1[0]; s.bp2[1] = s.bp1[1];
            s.bp2[2] = s.bp1[2]; s.bp2[3] = s.bp1[3];
            s.bp1[0] = b0; s.bp1[1] = b1; s.bp1[2] = b2; s.bp1[3] = b3;
            int sL = __shfl_up_sync(FULLM, s3, 1);
            int sR = __shfl_down_sync(FULLM, s0, 1);
            int n0 = sL + s0 + s1;
            int n1 = s0 + s1 + s2;
            int n2 = s1 + s2 + s3;
            int n3 = s2 + s3 + sR;
            const int wr = v - 1;
            if (writeok && wr >= Y0 && wr < Y0 + TH && (unsigned)wr < (unsigned)HH) {
                float4 o = make_float4(n0 >= 8 ? 1.f : 0.f, n1 >= 8 ? 1.f : 0.f,
                                       n2 >= 8 ? 1.f : 0.f, n3 >= 8 ? 1.f : 0.f);
                float* op = dp + (size_t)wr * WW + c0;
                *reinterpret_cast<float4*>(op) = o;
                if (dup) *reinterpret_cast<float4*>(op + NPIX) = o;
            }
        }
    }
}

template<bool FIN>
__device__ __noinline__ void run_gen(const float* sp, float* dp, int c0, int Y0,
                                     int lane, int dup,
                                     u64 kC1, u64 kC3, u64 kM7, u64 kM1)
{
    const int ecc = (lane == 0) ? (c0 - 4) : (c0 + 4);
    const bool isEdge = (lane == 0) || (lane == 31);
    const bool writeok = (lane >= 1) && (lane <= 30) && (c0 < WW);
    bool cv[4];
    #pragma unroll
    for (int k = 0; k < 4; ++k) cv[k] = (unsigned)(c0 + k) < (unsigned)WW;
    const int CFIRST = FIN ? (Y0 - 2) : (Y0 - 1);

    StG s;
    #pragma unroll
    for (int i = 0; i < 7; ++i) { s.a[i][0] = 0ull; s.a[i][1] = 0ull; }
    #pragma unroll
    for (int k = 0; k < 4; ++k) {
        s.cp[k] = NEGINF; s.pm[k] = NEGINF; s.bp1[k] = 0; s.bp2[k] = 0;
    }
    const int rs = FIN ? (Y0 - 5) : (Y0 - 4);
    s.ownN = ld4(sp, rs, c0);
    s.extN = isEdge ? ld4(sp, rs, ecc) : make_float4(0.f, 0.f, 0.f, 0.f);

    int r = rs;
    #pragma unroll 1
    for (int it = 0; it < NOUT; ++it) {
        step_gen<0, FIN>(s, sp, dp, r + 0, lane, c0, ecc, Y0, CFIRST, writeok, isEdge, cv, dup, kC1, kC3, kM7, kM1);
        step_gen<1, FIN>(s, sp, dp, r + 1, lane, c0, ecc, Y0, CFIRST, writeok, isEdge, cv, dup, kC1, kC3, kM7, kM1);
        step_gen<2, FIN>(s, sp, dp, r + 2, lane, c0, ecc, Y0, CFIRST, writeok, isEdge, cv, dup, kC1, kC3, kM7, kM1);
        step_gen<3, FIN>(s, sp, dp, r + 3, lane, c0, ecc, Y0, CFIRST, writeok, isEdge, cv, dup, kC1, kC3, kM7, kM1);
        step_gen<4, FIN>(s, sp, dp, r + 4, lane, c0, ecc, Y0, CFIRST, writeok, isEdge, cv, dup, kC1, kC3, kM7, kM1);
        step_gen<5, FIN>(s, sp, dp, r + 5, lane, c0, ecc, Y0, CFIRST, writeok, isEdge, cv, dup, kC1, kC3, kM7, kM1);
        step_gen<6, FIN>(s, sp, dp, r + 6, lane, c0, ecc, Y0, CFIRST, writeok, isEdge, cv, dup, kC1, kC3, kM7, kM1);
        r += 7;
    }
}

// ===================== combined kernel =====================
template<bool FIN>
__global__ void __launch_bounds__(32, 20) sweep(const float* __restrict__ src,
                                                float* __restrict__ dst,
                                                int dup)
{
    const int lane = threadIdx.x;
    const int sx = blockIdx.x;
    const int by = blockIdx.y;
    const int b  = blockIdx.z;
    const int Y0 = by * TH;
    const int c0 = 120 * sx - 4 + 4 * lane;
    const float* sp = src + (size_t)b * HH * WW;
    float* dp = dst + (size_t)b * HH * WW;

    u64 kC1, kC3, kM7, kM1;
    PK2(kC1, C1, C1); PK2(kC3, C3, C3); PK2(kM7, -C7, -C7); PK2(kM1, -1.0f, -1.0f);

    if (sx >= 1 && sx <= 7 && by >= 1 && by <= 30)
        run_int<FIN>(sp, dp, c0, Y0, lane, dup, kC1, kC3, kM7, kM1);
    else
        run_gen<FIN>(sp, dp, c0, Y0, lane, dup, kC1, kC3, kM7, kM1);
}

extern "C" void kernel_launch(void* const* d_in, const int* in_sizes, int n_in,
                              void* d_out, int out_size)
{
    const float* x = (const float*)d_in[0];
    float* out = (float*)d_out;

    float *A, *B;
    cudaGetSymbolAddress((void**)&A, g_bufA);
    cudaGetSymbolAddress((void**)&B, g_bufB);

    dim3 grid(9, HH / TH, NB);
    int dup = (out_size >= 2 * NPIX) ? 1 : 0;

    sweep<false><<<grid, 32>>>(x, A, 0);
    sweep<false><<<grid, 32>>>(A, B, 0);
    sweep<false><<<grid, 32>>>(B, A, 0);
    sweep<true ><<<grid, 32>>>(A, out, dup);
}